// round 15
// baseline (speedup 1.0000x reference)
#include <cuda_runtime.h>

#define PMAX 32
#define COUT 64
#define GRID 296
#define NTHR 512
#define NWARP 16
#define BATCH 4
#define EPSV 1e-5f

// Scratch (no allocations): per-block partials + barrier/queue state.
__device__ float g_part[GRID * 16];
__device__ unsigned g_count = 0;     // arrive counter (returns to 0 each launch)
__device__ unsigned g_release = 0;   // monotonically increasing generation
__device__ unsigned g_next = 0;      // phase-B work cursor (reset each launch)

typedef unsigned long long u64;

__device__ __forceinline__ u64 pk2(float a, float b) {
    u64 r; asm("mov.b64 %0, {%1,%2};" : "=l"(r) : "f"(a), "f"(b)); return r;
}
__device__ __forceinline__ void upk2(u64 v, float& a, float& b) {
    asm("mov.b64 {%0,%1}, %2;" : "=f"(a), "=f"(b) : "l"(v));
}
__device__ __forceinline__ u64 fma2(u64 a, u64 b, u64 c) {
    u64 d; asm("fma.rn.f32x2 %0, %1, %2, %3;" : "=l"(d) : "l"(a), "l"(b), "l"(c)); return d;
}
__device__ __forceinline__ u64 add2(u64 a, u64 b) {
    u64 d; asm("add.rn.f32x2 %0, %1, %2;" : "=l"(d) : "l"(a), "l"(b)); return d;
}

__global__ void __launch_bounds__(NTHR, 2) fused_kernel(
    const float* __restrict__ feat, const int* __restrict__ npts,
    const float* __restrict__ W, const float* __restrict__ b,
    const float* __restrict__ gamma, const float* __restrict__ beta,
    float* __restrict__ out, int M)
{
    __shared__ float red[32][16];
    __shared__ float fin[16];
    __shared__ __align__(16) float sp[NWARP][16 * 12 + 16];  // per-warp staging (+pad)

    int tid = threadIdx.x;
    int w = tid >> 5, l = tid & 31;

    // ===== Phase A: UNIFORM unconditional streaming stats (no staging) ======
    const int T = M * PMAX;
    const int S = GRID * NTHR;          // 151552 threads
    float cnt = 0.f;
    float s0=0,s1=0,s2=0,s3=0;
    float q00=0,q01=0,q02=0,q03=0,q11=0,q12=0,q13=0,q22=0,q23=0,q33=0;

    int gt = blockIdx.x * NTHR + tid;
    for (int base = gt; base < T; base += 4 * S) {
        float4 v[4]; int n[4]; int p[4]; bool in[4];
        #pragma unroll
        for (int u = 0; u < 4; u++) {
            int i = base + u * S;
            in[u] = (i < T);
            if (in[u]) {
                v[u] = __ldg(&((const float4*)feat)[i]);   // independent LDGs (MLP)
                n[u] = __ldg(&npts[i >> 5]);                // warp-uniform broadcast
                p[u] = i & 31;
            }
        }
        #pragma unroll
        for (int u = 0; u < 4; u++) {
            bool ok = in[u] && (p[u] < n[u]);
            float x = ok ? v[u].x : 0.f;
            float y = ok ? v[u].y : 0.f;
            float z = ok ? v[u].z : 0.f;
            float ww = ok ? v[u].w : 0.f;
            cnt += ok ? 1.f : 0.f;
            s0 += x; s1 += y; s2 += z; s3 += ww;
            q00 += x*x; q01 += x*y; q02 += x*z; q03 += x*ww;
            q11 += y*y; q12 += y*z; q13 += y*ww;
            q22 += z*z; q23 += z*ww; q33 += ww*ww;
        }
    }

    float vals[15] = {cnt, s0,s1,s2,s3, q00,q01,q02,q03,q11,q12,q13,q22,q23,q33};
    #pragma unroll
    for (int k = 0; k < 15; k++) {
        #pragma unroll
        for (int off = 16; off > 0; off >>= 1)
            vals[k] += __shfl_down_sync(0xffffffffu, vals[k], off);
    }
    if (l == 0) {
        #pragma unroll
        for (int k = 0; k < 15; k++) red[w][k] = vals[k];
    }
    __syncthreads();
    if (tid < 15) {
        float t = 0.f;
        #pragma unroll
        for (int ww = 0; ww < NWARP; ww++) t += red[ww][tid];
        g_part[blockIdx.x * 16 + tid] = t;
    }
    // Reset phase-B cursor before the barrier (ordered by barrier release).
    if (blockIdx.x == 0 && tid == 0) g_next = 0;
    if (tid < 16) __threadfence();
    __syncthreads();

    // ================= Grid barrier (deterministic) =========================
    if (tid == 0) {
        unsigned old = *((volatile unsigned*)&g_release);
        unsigned a = atomicAdd(&g_count, 1);
        if (a == gridDim.x - 1) {
            g_count = 0;
            __threadfence();
            *((volatile unsigned*)&g_release) = old + 1;
        } else {
            while (*((volatile unsigned*)&g_release) == old) { }
            __threadfence();
        }
    }
    __syncthreads();

    // ================= Fold: every block reduces all partials ===============
    {
        int stat = tid & 15, grp = tid >> 4;     // 32 groups of 16 stats
        float s = 0.f;
        for (int k = grp; k < GRID; k += 32)
            s += g_part[k * 16 + stat];
        red[grp][stat] = s;
    }
    __syncthreads();
    if (tid < 16) {
        float tt = 0.f;
        #pragma unroll
        for (int g = 0; g < 32; g++) tt += red[g][tid];
        fin[tid] = tt;
    }
    __syncthreads();

    // Per-thread BN fold for channels o0 = l and o1 = l + 32.
    float N  = fmaxf(fin[0], 1.f);
    float invN = 1.f / N;
    float S0 = fin[1], S1 = fin[2], S2 = fin[3], S3 = fin[4];
    float f00=fin[5], f01=fin[6], f02=fin[7], f03=fin[8];
    float f11=fin[9], f12=fin[10], f13=fin[11];
    float f22=fin[12], f23=fin[13], f33=fin[14];

    u64 WA0, WA1, WA2, WA3, WB0, WB1, WB2, WB3, BA, BB;
    float relu0A, relu0B;
    #pragma unroll
    for (int half = 0; half < 2; half++) {
        int o = l + half * 32;
        float w0 = __ldg(&W[o*4+0]), w1 = __ldg(&W[o*4+1]);
        float w2 = __ldg(&W[o*4+2]), w3 = __ldg(&W[o*4+3]);
        float bo = __ldg(&b[o]);
        float wS = w0*S0 + w1*S1 + w2*S2 + w3*S3;
        float mu = (wS + bo * N) * invN;
        float wQw = w0*(f00*w0 + f01*w1 + f02*w2 + f03*w3)
                  + w1*(f01*w0 + f11*w1 + f12*w2 + f13*w3)
                  + w2*(f02*w0 + f12*w1 + f22*w2 + f23*w3)
                  + w3*(f03*w0 + f13*w1 + f23*w2 + f33*w3);
        float Eh2 = (wQw + 2.f*bo*wS + bo*bo*N) * invN;
        float var = fmaxf(Eh2 - mu*mu, 0.f);
        float sc  = __ldg(&gamma[o]) * rsqrtf(var + EPSV);
        float bf  = sc * (bo - mu) + __ldg(&beta[o]);
        if (half == 0) {
            WA0 = pk2(sc*w0, sc*w0); WA1 = pk2(sc*w1, sc*w1);
            WA2 = pk2(sc*w2, sc*w2); WA3 = pk2(sc*w3, sc*w3);
            BA = pk2(bf, bf); relu0A = fmaxf(bf, 0.f);
        } else {
            WB0 = pk2(sc*w0, sc*w0); WB1 = pk2(sc*w1, sc*w1);
            WB2 = pk2(sc*w2, sc*w2); WB3 = pk2(sc*w3, sc*w3);
            BB = pk2(bf, bf); relu0B = fmaxf(bf, 0.f);
        }
    }
    const u64 ABSM = 0x7FFFFFFF7FFFFFFFULL;

    // ===== Phase B: work-stealing queue, warp-per-voxel GEMV ================
    float* s = sp[w];
    // Zero the staging buffer once (covers padded slots for all voxels).
    #pragma unroll
    for (int k = l; k < 16 * 12 + 16; k += 32) s[k] = 0.f;
    __syncwarp();

    for (;;) {
        unsigned base;
        if (l == 0) base = atomicAdd(&g_next, BATCH);
        base = __shfl_sync(0xffffffffu, base, 0);
        if ((int)base >= M) break;
        int mend = min((int)base + BATCH, M);

        for (int m = (int)base; m < mend; m++) {
            int n = __ldg(&npts[m]);                 // warp-uniform broadcast

            __syncwarp();                            // prior reads done
            if (l < n) {
                float4 v = __ldg(&((const float4*)feat)[(size_t)m * PMAX + l]);
                float* d = s + (l >> 1) * 12 + (l & 1);
                d[0] = v.x; d[2] = v.y; d[4] = v.z; d[6] = v.w;
            }
            __syncwarp();

            int P = (n + 1) >> 1;                    // exact pairs (half slot is zero*)
            // (*odd n: slot n is stale from an earlier voxel? No — see below:
            //  we clear it explicitly when n is odd.)
            if ((n & 1) && l == 0) {
                // clear the odd companion slot (may hold stale data)
                float* d = s + ((n - 1) >> 1) * 12 + 1;
                d[0] = 0.f; d[2] = 0.f; d[4] = 0.f; d[6] = 0.f;
            }
            // also clear nothing else: j < P only touches pairs < P, and pairs
            // >= P from previous voxels are never read for this voxel.
            __syncwarp();

            const ulonglong2* q = reinterpret_cast<const ulonglong2*>(s);
            ulonglong2 c0 = q[0], c1 = q[1];
            u64 SHA = 0ULL, SABA = 0ULL, SHB = 0ULL, SABB = 0ULL;
            for (int j = 0; j < P; j++) {
                const ulonglong2* qn = reinterpret_cast<const ulonglong2*>(s + (j + 1) * 12);
                ulonglong2 n0 = qn[0], n1 = qn[1];
                u64 hA = fma2(WA0, c0.x, BA);
                u64 hB = fma2(WB0, c0.x, BB);
                hA = fma2(WA1, c0.y, hA);
                hB = fma2(WB1, c0.y, hB);
                hA = fma2(WA2, c1.x, hA);
                hB = fma2(WB2, c1.x, hB);
                hA = fma2(WA3, c1.y, hA);
                hB = fma2(WB3, c1.y, hB);
                SHA  = add2(SHA, hA);
                SABA = add2(SABA, hA & ABSM);
                SHB  = add2(SHB, hB);
                SABB = add2(SABB, hB & ABSM);
                c0 = n0; c1 = n1;
            }

            float r0, r1, r2, r3;
            upk2(SHA, r0, r1); upk2(SABA, r2, r3);
            float acc0 = 0.5f * ((r0 + r1) + (r2 + r3));
            upk2(SHB, r0, r1); upk2(SABB, r2, r3);
            float acc1 = 0.5f * ((r0 + r1) + (r2 + r3));

            float extra = (float)(2 * P - n);        // 0 or 1 padded zero slots
            acc0 = fmaf(-extra, relu0A, acc0);
            acc1 = fmaf(-extra, relu0B, acc1);

            float inv = 1.f / fmaxf((float)n, 1.f);
            out[(size_t)m * COUT + l]      = acc0 * inv;
            out[(size_t)m * COUT + 32 + l] = acc1 * inv;
        }
    }
}

// ---------------------------------------------------------------------------
extern "C" void kernel_launch(void* const* d_in, const int* in_sizes, int n_in,
                              void* d_out, int out_size)
{
    const float* feat  = (const float*)d_in[0];
    const int*   npts  = (const int*)d_in[1];
    const float* W     = (const float*)d_in[2];
    const float* b     = (const float*)d_in[3];
    const float* gamma = (const float*)d_in[4];
    const float* beta  = (const float*)d_in[5];
    float* out = (float*)d_out;
    int M = in_sizes[1];

    fused_kernel<<<GRID, NTHR>>>(feat, npts, W, b, gamma, beta, out, M);
}